// round 8
// baseline (speedup 1.0000x reference)
#include <cuda_runtime.h>
#include <cuda_bf16.h>
#include <cstdint>

#define NN 50000
#define NE 800000
#define NF 96
#define NC 40

#define SCAN_TB 256
#define SCAN_BLOCKS ((NN + SCAN_TB - 1) / SCAN_TB)   // 196

// ---------------- flat static device scratch ----------------
#define OFF_DEG      0
#define OFF_DINV     (OFF_DEG + NN)
#define OFF_COUNTS   (OFF_DINV + NN)
#define OFF_CURSOR   (OFF_COUNTS + NN)
#define OFF_OFFSETS  (OFF_CURSOR + NN)              // NN+1 ints
#define OFF_FLAGS    (OFF_OFFSETS + NN + 8)         // 4 ints
#define OFF_BSUM     (OFF_FLAGS + 8)                // 256 ints
#define OFF_PAIR_SGC (OFF_BSUM + 256)               // NE int2 (src, norm)
#define OFF_PAIR_LPA (OFF_PAIR_SGC + 2 * NE)        // NE int2 (src, ew)
#define OFF_Z0       (OFF_PAIR_LPA + 2 * NE)        // NN*NC
#define OFF_Z1       (OFF_Z0 + NN * NC)
#define OFF_L0       (OFF_Z1 + NN * NC)
#define OFF_L1       (OFF_L0 + NN * NC)
#define SCRATCH_ELEMS (OFF_L1 + NN * NC + 64)

__device__ __align__(256) float g_scratch[SCRATCH_ELEMS];

// flags[0]: edge_index is int64; flags[1]: mask is 4-byte; flags[2]: y is int64
__device__ __forceinline__ int load_idx(const void* p, long long i, int is64) {
    return is64 ? (int)((const long long*)p)[i] : ((const int*)p)[i];
}

// ---------------- K1: init + sniff + gemm (z = x @ W, NO bias) ----------------
#define GEMM_ROWS 32
#define GEMM_BLOCKS ((NN + GEMM_ROWS - 1) / GEMM_ROWS)   // 1563
#define INIT_BLOCKS ((NN + 255) / 256)                    // 196

__global__ void init_sniff_gemm_kernel(float* __restrict__ deg,
                                       int* __restrict__ counts,
                                       int* __restrict__ flags,
                                       const void* __restrict__ ei,
                                       const void* __restrict__ y,
                                       const void* __restrict__ mask,
                                       const float* __restrict__ x,
                                       const float* __restrict__ W,
                                       float* __restrict__ z) {
    if (blockIdx.x < INIT_BLOCKS) {
        int i = blockIdx.x * blockDim.x + threadIdx.x;
        if (i < NN) { deg[i] = 1.0f; counts[i] = 0; }
        if (blockIdx.x == 0) {
            __shared__ int narrow[3];
            int tid = threadIdx.x;
            if (tid < 3) narrow[tid] = 0;
            __syncthreads();
            const int* ei32 = (const int*)ei;
            const int* y32  = (const int*)y;
            const unsigned char* m8 = (const unsigned char*)mask;
            if (ei32[2 * tid + 1] != 0) narrow[0] = 1;
            if (y32[2 * tid + 1]  != 0) narrow[2] = 1;
            for (int t = tid; t < 4096; t += 256)
                if ((t & 3) != 0 && m8[t] != 0) narrow[1] = 1;
            __syncthreads();
            if (tid < 3) flags[tid] = narrow[tid] ? 0 : 1;
        }
    } else {
        __shared__ float sW[NF * NC];
        __shared__ float sH[GEMM_ROWS * NF];
        int tid = threadIdx.x;
        int row0 = (blockIdx.x - INIT_BLOCKS) * GEMM_ROWS;
        for (int i = tid; i < NF * NC; i += 256) sW[i] = W[i];
        int nrows = min(GEMM_ROWS, NN - row0);
        int nelem = nrows * NF;
        const float* hp = x + (size_t)row0 * NF;
        for (int i = tid; i < nelem; i += 256) sH[i] = hp[i];
        __syncthreads();
        int nout = nrows * NC;
        for (int o = tid; o < nout; o += 256) {
            int r = o / NC, c = o % NC;
            float acc = 0.0f;
            const float* hr = &sH[r * NF];
            #pragma unroll 8
            for (int k = 0; k < NF; k++) acc += hr[k] * sW[k * NC + c];
            z[(size_t)(row0 + r) * NC + c] = acc;
        }
    }
}

__global__ void deg_count_kernel(const void* __restrict__ ei,
                                 const float* __restrict__ ew,
                                 float* __restrict__ deg,
                                 int* __restrict__ counts,
                                 const int* __restrict__ flags) {
    int e = blockIdx.x * blockDim.x + threadIdx.x;
    if (e < NE) {
        int c = load_idx(ei, (long long)NE + e, flags[0]);
        if ((unsigned)c < NN) {
            atomicAdd(&deg[c], ew[e]);
            atomicAdd(&counts[c], 1);
        }
    }
}

__global__ void scanA_kernel(const int* __restrict__ counts,
                             const float* __restrict__ deg,
                             float* __restrict__ dinv,
                             int* __restrict__ bsum) {
    __shared__ int sh[SCAN_TB];
    int i = blockIdx.x * SCAN_TB + threadIdx.x;
    int v = (i < NN) ? counts[i] : 0;
    if (i < NN) dinv[i] = rsqrtf(deg[i]);
    sh[threadIdx.x] = v;
    __syncthreads();
    for (int off = SCAN_TB / 2; off > 0; off >>= 1) {
        if (threadIdx.x < off) sh[threadIdx.x] += sh[threadIdx.x + off];
        __syncthreads();
    }
    if (threadIdx.x == 0) bsum[blockIdx.x] = sh[0];
}

__global__ void scanB_kernel(int* __restrict__ bsum, int* __restrict__ offsets) {
    __shared__ int sh[SCAN_TB];
    int t = threadIdx.x;
    int v = (t < SCAN_BLOCKS) ? bsum[t] : 0;
    sh[t] = v;
    __syncthreads();
    for (int off = 1; off < SCAN_TB; off <<= 1) {
        int u = (t >= off) ? sh[t - off] : 0;
        __syncthreads();
        sh[t] += u;
        __syncthreads();
    }
    if (t < SCAN_BLOCKS) bsum[t] = sh[t] - v;
    if (t == SCAN_BLOCKS - 1) offsets[NN] = sh[t];
}

__global__ void scanC_kernel(const int* __restrict__ counts,
                             const int* __restrict__ bsum,
                             int* __restrict__ offsets,
                             int* __restrict__ cursor) {
    __shared__ int sh[SCAN_TB];
    int i = blockIdx.x * SCAN_TB + threadIdx.x;
    int v = (i < NN) ? counts[i] : 0;
    sh[threadIdx.x] = v;
    __syncthreads();
    for (int off = 1; off < SCAN_TB; off <<= 1) {
        int u = (threadIdx.x >= off) ? sh[threadIdx.x - off] : 0;
        __syncthreads();
        sh[threadIdx.x] += u;
        __syncthreads();
    }
    if (i < NN) {
        int excl = bsum[blockIdx.x] + sh[threadIdx.x] - v;
        offsets[i] = excl;
        cursor[i]  = excl;
    }
}

#define FILL_BLOCKS  ((NE + 255) / 256)
#define LINIT_BLOCKS ((NN * NC + 255) / 256)

__global__ void fill_lpainit_kernel(const void* __restrict__ ei,
                                    const float* __restrict__ ew,
                                    const float* __restrict__ dinv,
                                    int* __restrict__ cursor,
                                    int2* __restrict__ ps,
                                    int2* __restrict__ pl,
                                    const void* __restrict__ y,
                                    const void* __restrict__ mask,
                                    float* __restrict__ l0,
                                    const int* __restrict__ flags) {
    if (blockIdx.x < FILL_BLOCKS) {
        int e = blockIdx.x * blockDim.x + threadIdx.x;
        if (e < NE) {
            int is64 = flags[0];
            int r = load_idx(ei, e, is64);
            int c = load_idx(ei, (long long)NE + e, is64);
            if ((unsigned)r < NN && (unsigned)c < NN) {
                int pos = atomicAdd(&cursor[c], 1);
                if ((unsigned)pos < NE) {
                    float w = ew[e];
                    ps[pos] = make_int2(r, __float_as_int(dinv[r] * w * dinv[c]));
                    pl[pos] = make_int2(r, __float_as_int(w));
                }
            }
        }
    } else {
        int idx = (blockIdx.x - FILL_BLOCKS) * blockDim.x + threadIdx.x;
        if (idx < NN * NC) {
            int n = idx / NC, c = idx % NC;
            int yv = load_idx(y, n, flags[2]);
            int mv = flags[1] ? ((const int*)mask)[n]
                              : (int)((const unsigned char*)mask)[n];
            l0[idx] = (mv != 0 && yv == c) ? 1.0f : 0.0f;
        }
    }
}

// ---------------- 40-wide propagate, metadata-prefetched ----------------
// Warp per node. Coalesced per-lane metadata load (32 edges/load) into regs;
// loop consumes metadata via shfl (no memory on the dependent path). Lanes
// 0-29 in 3 groups of 10; each group gathers one 160B row per step; 4 steps
// unrolled with independent accumulators -> 12 gathers in flight.
template <bool SELF, bool BIAS>
__device__ __forceinline__ void prop40(int n, int lane,
                                       const float* __restrict__ in,
                                       float* __restrict__ out,
                                       const float* __restrict__ dinv,
                                       const float* __restrict__ bias,
                                       const int* __restrict__ offsets,
                                       const int2* __restrict__ pr) {
    const unsigned FULL = 0xFFFFFFFFu;
    int grp = lane / 10;           // 0..2 active; lanes 30,31 idle for gathers
    int sub = lane - grp * 10;     // 0..9
    bool active = (lane < 30);
    int beg = offsets[n], end = offsets[n + 1];

    float4 a0 = make_float4(0.f,0.f,0.f,0.f);
    float4 a1 = a0, a2 = a0, a3 = a0;

    for (int base = beg; base < end; base += 32) {
        int cnt = end - base; if (cnt > 32) cnt = 32;
        int2 meta = make_int2(0, 0);
        if (lane < cnt) meta = pr[base + lane];    // coalesced 8B/lane

        int j = 0;
        for (; j + 12 <= cnt; j += 12) {
            int   s0 = __shfl_sync(FULL, meta.x, j + grp);
            float w0 = __int_as_float(__shfl_sync(FULL, meta.y, j + grp));
            int   s1 = __shfl_sync(FULL, meta.x, j + 3 + grp);
            float w1 = __int_as_float(__shfl_sync(FULL, meta.y, j + 3 + grp));
            int   s2 = __shfl_sync(FULL, meta.x, j + 6 + grp);
            float w2 = __int_as_float(__shfl_sync(FULL, meta.y, j + 6 + grp));
            int   s3 = __shfl_sync(FULL, meta.x, j + 9 + grp);
            float w3 = __int_as_float(__shfl_sync(FULL, meta.y, j + 9 + grp));
            if (active) {
                float4 v0 = ((const float4*)(in + (size_t)s0 * NC))[sub];
                float4 v1 = ((const float4*)(in + (size_t)s1 * NC))[sub];
                float4 v2 = ((const float4*)(in + (size_t)s2 * NC))[sub];
                float4 v3 = ((const float4*)(in + (size_t)s3 * NC))[sub];
                a0.x += w0*v0.x; a0.y += w0*v0.y; a0.z += w0*v0.z; a0.w += w0*v0.w;
                a1.x += w1*v1.x; a1.y += w1*v1.y; a1.z += w1*v1.z; a1.w += w1*v1.w;
                a2.x += w2*v2.x; a2.y += w2*v2.y; a2.z += w2*v2.z; a2.w += w2*v2.w;
                a3.x += w3*v3.x; a3.y += w3*v3.y; a3.z += w3*v3.z; a3.w += w3*v3.w;
            }
        }
        for (; j < cnt; j += 3) {
            int idx = j + grp;
            int sel = (idx < cnt) ? idx : 0;
            int   s = __shfl_sync(FULL, meta.x, sel);
            float w = __int_as_float(__shfl_sync(FULL, meta.y, sel));
            if (active && idx < cnt) {
                float4 v = ((const float4*)(in + (size_t)s * NC))[sub];
                a0.x += w*v.x; a0.y += w*v.y; a0.z += w*v.z; a0.w += w*v.w;
            }
        }
    }

    float4 acc;
    acc.x = (a0.x + a1.x) + (a2.x + a3.x);
    acc.y = (a0.y + a1.y) + (a2.y + a3.y);
    acc.z = (a0.z + a1.z) + (a2.z + a3.z);
    acc.w = (a0.w + a1.w) + (a2.w + a3.w);

    // combine group partials: lanes 0-9 += lanes 10-19, 20-29
    const unsigned m = 0xFFFFFFFFu;
    float t1, t2;
    t1 = __shfl_sync(m, acc.x, lane + 10); t2 = __shfl_sync(m, acc.x, lane + 20);
    acc.x += t1 + t2;
    t1 = __shfl_sync(m, acc.y, lane + 10); t2 = __shfl_sync(m, acc.y, lane + 20);
    acc.y += t1 + t2;
    t1 = __shfl_sync(m, acc.z, lane + 10); t2 = __shfl_sync(m, acc.z, lane + 20);
    acc.z += t1 + t2;
    t1 = __shfl_sync(m, acc.w, lane + 10); t2 = __shfl_sync(m, acc.w, lane + 20);
    acc.w += t1 + t2;

    if (lane < 10) {
        if (SELF) {
            float dii = dinv[n]; dii *= dii;
            float4 v = ((const float4*)(in + (size_t)n * NC))[lane];
            acc.x += dii * v.x; acc.y += dii * v.y;
            acc.z += dii * v.z; acc.w += dii * v.w;
        }
        if (BIAS) {
            float4 bb = ((const float4*)bias)[lane];
            acc.x += bb.x; acc.y += bb.y; acc.z += bb.z; acc.w += bb.w;
        }
        ((float4*)(out + (size_t)n * NC))[lane] = acc;
    }
}

#define PROP_BLOCKS ((NN + 7) / 8)    // 6250 blocks, warp per node

template <bool LAST>
__global__ __launch_bounds__(256) void prop_pair_kernel(
        const float* __restrict__ sgc_in, float* __restrict__ sgc_out,
        const float* __restrict__ lpa_in, float* __restrict__ lpa_out,
        const float* __restrict__ dinv, const float* __restrict__ bias,
        const int* __restrict__ offsets,
        const int2* __restrict__ ps, const int2* __restrict__ pl) {
    int lane = threadIdx.x & 31;
    int wib  = threadIdx.x >> 5;
    if (blockIdx.x < PROP_BLOCKS) {
        int n = blockIdx.x * 8 + wib;
        if (n < NN) prop40<true, LAST>(n, lane, sgc_in, sgc_out, dinv, bias, offsets, ps);
    } else {
        int n = (blockIdx.x - PROP_BLOCKS) * 8 + wib;
        if (n < NN) prop40<false, false>(n, lane, lpa_in, lpa_out, dinv, bias, offsets, pl);
    }
}

__global__ __launch_bounds__(256) void lpa_final_kernel(
        const float* __restrict__ in, float* __restrict__ out,
        const int* __restrict__ offsets, const int2* __restrict__ pl) {
    int lane = threadIdx.x & 31;
    int n = blockIdx.x * 8 + (threadIdx.x >> 5);
    if (n < NN) prop40<false, false>(n, lane, in, out, nullptr, nullptr, offsets, pl);
}

// ---------------- launch ----------------

extern "C" void kernel_launch(void* const* d_in, const int* in_sizes, int n_in,
                              void* d_out, int out_size) {
    const float* x    = (const float*)d_in[0];
    const void*  ei   = d_in[1];
    const void*  y    = d_in[2];
    const void*  mask = d_in[3];
    const float* ew   = (const float*)d_in[4];
    const float* W    = (const float*)d_in[5];
    const float* b    = (const float*)d_in[6];
    float* out = (float*)d_out;
    float* x_out   = out;
    float* lpa_out = out + NN * NC;

    static float* s = nullptr;
    if (s == nullptr) {
        void* p = nullptr;
        cudaGetSymbolAddress(&p, g_scratch);
        s = (float*)p;
    }
    float* deg     = s + OFF_DEG;
    float* dinv    = s + OFF_DINV;
    int*   counts  = (int*)(s + OFF_COUNTS);
    int*   cursor  = (int*)(s + OFF_CURSOR);
    int*   offsets = (int*)(s + OFF_OFFSETS);
    int*   flags   = (int*)(s + OFF_FLAGS);
    int*   bsum    = (int*)(s + OFF_BSUM);
    int2*  ps      = (int2*)(s + OFF_PAIR_SGC);
    int2*  pl      = (int2*)(s + OFF_PAIR_LPA);
    float* z0      = s + OFF_Z0;
    float* z1      = s + OFF_Z1;
    float* l0      = s + OFF_L0;
    float* l1      = s + OFF_L1;

    const int TB = 256;
    int gE = (NE + TB - 1) / TB;

    init_sniff_gemm_kernel<<<INIT_BLOCKS + GEMM_BLOCKS, TB>>>(
        deg, counts, flags, ei, y, mask, x, W, z0);
    deg_count_kernel<<<gE, TB>>>(ei, ew, deg, counts, flags);
    scanA_kernel<<<SCAN_BLOCKS, SCAN_TB>>>(counts, deg, dinv, bsum);
    scanB_kernel<<<1, SCAN_TB>>>(bsum, offsets);
    scanC_kernel<<<SCAN_BLOCKS, SCAN_TB>>>(counts, bsum, offsets, cursor);
    fill_lpainit_kernel<<<FILL_BLOCKS + LINIT_BLOCKS, TB>>>(
        ei, ew, dinv, cursor, ps, pl, y, mask, l0, flags);

    prop_pair_kernel<false><<<2 * PROP_BLOCKS, TB>>>(
        z0, z1, l0, l1, dinv, b, offsets, ps, pl);
    prop_pair_kernel<true><<<2 * PROP_BLOCKS, TB>>>(
        z1, x_out, l1, l0, dinv, b, offsets, ps, pl);
    lpa_final_kernel<<<PROP_BLOCKS, TB>>>(l0, lpa_out, offsets, pl);

    (void)in_sizes; (void)n_in; (void)out_size;
}

// round 9
// speedup vs baseline: 1.0006x; 1.0006x over previous
#include <cuda_runtime.h>
#include <cuda_bf16.h>
#include <cstdint>

#define NN 50000
#define NE 800000
#define NF 96
#define NC 40

#define SCAN_TB 256
#define SCAN_BLOCKS ((NN + SCAN_TB - 1) / SCAN_TB)   // 196

// ---------------- flat static device scratch ----------------
#define OFF_DEG      0
#define OFF_DINV     (OFF_DEG + NN)
#define OFF_COUNTS   (OFF_DINV + NN)
#define OFF_CURSOR   (OFF_COUNTS + NN)
#define OFF_OFFSETS  (OFF_CURSOR + NN)              // NN+1 ints
#define OFF_FLAGS    (OFF_OFFSETS + NN + 8)         // 4 ints
#define OFF_BSUM     (OFF_FLAGS + 8)                // 256 ints
#define OFF_PAIR_SGC (OFF_BSUM + 256)               // NE int2 (src, norm)
#define OFF_PAIR_LPA (OFF_PAIR_SGC + 2 * NE)        // NE int2 (src, ew)
#define OFF_Z0       (OFF_PAIR_LPA + 2 * NE)        // NN*NC
#define OFF_Z1       (OFF_Z0 + NN * NC)
#define OFF_L0       (OFF_Z1 + NN * NC)
#define OFF_L1       (OFF_L0 + NN * NC)
#define SCRATCH_ELEMS (OFF_L1 + NN * NC + 64)

__device__ __align__(256) float g_scratch[SCRATCH_ELEMS];

// flags[0]: edge_index is int64; flags[1]: mask is 4-byte; flags[2]: y is int64
__device__ __forceinline__ int load_idx(const void* p, long long i, int is64) {
    return is64 ? (int)((const long long*)p)[i] : ((const int*)p)[i];
}

// ---------------- K1: init + sniff + gemm (z = x @ W, NO bias) ----------------
#define GEMM_ROWS 32
#define GEMM_BLOCKS ((NN + GEMM_ROWS - 1) / GEMM_ROWS)   // 1563
#define INIT_BLOCKS ((NN + 255) / 256)                    // 196

__global__ void init_sniff_gemm_kernel(float* __restrict__ deg,
                                       int* __restrict__ counts,
                                       int* __restrict__ flags,
                                       const void* __restrict__ ei,
                                       const void* __restrict__ y,
                                       const void* __restrict__ mask,
                                       const float* __restrict__ x,
                                       const float* __restrict__ W,
                                       float* __restrict__ z) {
    if (blockIdx.x < INIT_BLOCKS) {
        int i = blockIdx.x * blockDim.x + threadIdx.x;
        if (i < NN) { deg[i] = 1.0f; counts[i] = 0; }
        if (blockIdx.x == 0) {
            __shared__ int narrow[3];
            int tid = threadIdx.x;
            if (tid < 3) narrow[tid] = 0;
            __syncthreads();
            const int* ei32 = (const int*)ei;
            const int* y32  = (const int*)y;
            const unsigned char* m8 = (const unsigned char*)mask;
            if (ei32[2 * tid + 1] != 0) narrow[0] = 1;
            if (y32[2 * tid + 1]  != 0) narrow[2] = 1;
            for (int t = tid; t < 4096; t += 256)
                if ((t & 3) != 0 && m8[t] != 0) narrow[1] = 1;
            __syncthreads();
            if (tid < 3) flags[tid] = narrow[tid] ? 0 : 1;
        }
    } else {
        __shared__ float sW[NF * NC];
        __shared__ float sH[GEMM_ROWS * NF];
        int tid = threadIdx.x;
        int row0 = (blockIdx.x - INIT_BLOCKS) * GEMM_ROWS;
        for (int i = tid; i < NF * NC; i += 256) sW[i] = W[i];
        int nrows = min(GEMM_ROWS, NN - row0);
        int nelem = nrows * NF;
        const float* hp = x + (size_t)row0 * NF;
        for (int i = tid; i < nelem; i += 256) sH[i] = hp[i];
        __syncthreads();
        int nout = nrows * NC;
        for (int o = tid; o < nout; o += 256) {
            int r = o / NC, c = o % NC;
            float acc = 0.0f;
            const float* hr = &sH[r * NF];
            #pragma unroll 8
            for (int k = 0; k < NF; k++) acc += hr[k] * sW[k * NC + c];
            z[(size_t)(row0 + r) * NC + c] = acc;
        }
    }
}

__global__ void deg_count_kernel(const void* __restrict__ ei,
                                 const float* __restrict__ ew,
                                 float* __restrict__ deg,
                                 int* __restrict__ counts,
                                 const int* __restrict__ flags) {
    int e = blockIdx.x * blockDim.x + threadIdx.x;
    if (e < NE) {
        int c = load_idx(ei, (long long)NE + e, flags[0]);
        if ((unsigned)c < NN) {
            atomicAdd(&deg[c], ew[e]);
            atomicAdd(&counts[c], 1);
        }
    }
}

// ---- Phase A: per-block reduce of counts + fused dinv ----
__global__ void scanA_kernel(const int* __restrict__ counts,
                             const float* __restrict__ deg,
                             float* __restrict__ dinv,
                             int* __restrict__ bsum) {
    __shared__ int sh[SCAN_TB];
    int i = blockIdx.x * SCAN_TB + threadIdx.x;
    int v = (i < NN) ? counts[i] : 0;
    if (i < NN) dinv[i] = rsqrtf(deg[i]);
    sh[threadIdx.x] = v;
    __syncthreads();
    for (int off = SCAN_TB / 2; off > 0; off >>= 1) {
        if (threadIdx.x < off) sh[threadIdx.x] += sh[threadIdx.x + off];
        __syncthreads();
    }
    if (threadIdx.x == 0) bsum[blockIdx.x] = sh[0];
}

// ---- Phase BC merged: every block redundantly scans the 196 block sums,
// then does its local scan + prefix. Removes one launch.
__global__ void scanBC_kernel(const int* __restrict__ counts,
                              const int* __restrict__ bsum,
                              int* __restrict__ offsets,
                              int* __restrict__ cursor) {
    __shared__ int sb[SCAN_TB];
    __shared__ int sh[SCAN_TB];
    int t = threadIdx.x;
    int bv = (t < SCAN_BLOCKS) ? bsum[t] : 0;
    sb[t] = bv;
    __syncthreads();
    for (int off = 1; off < SCAN_TB; off <<= 1) {
        int u = (t >= off) ? sb[t - off] : 0;
        __syncthreads();
        sb[t] += u;
        __syncthreads();
    }
    // sb[k] = inclusive sum of bsum[0..k]
    int blockPrefix = (blockIdx.x == 0) ? 0 : sb[blockIdx.x - 1];
    if (blockIdx.x == 0 && t == 0) offsets[NN] = sb[SCAN_BLOCKS - 1];

    int i = blockIdx.x * SCAN_TB + t;
    int v = (i < NN) ? counts[i] : 0;
    sh[t] = v;
    __syncthreads();
    for (int off = 1; off < SCAN_TB; off <<= 1) {
        int u = (t >= off) ? sh[t - off] : 0;
        __syncthreads();
        sh[t] += u;
        __syncthreads();
    }
    if (i < NN) {
        int excl = blockPrefix + sh[t] - v;
        offsets[i] = excl;
        cursor[i]  = excl;
    }
}

// ---- fill CSR (+ fused LPA one-hot init) ----
#define FILL_BLOCKS  ((NE + 255) / 256)
#define LINIT_BLOCKS ((NN * NC + 255) / 256)

__global__ void fill_lpainit_kernel(const void* __restrict__ ei,
                                    const float* __restrict__ ew,
                                    const float* __restrict__ dinv,
                                    int* __restrict__ cursor,
                                    int2* __restrict__ ps,
                                    int2* __restrict__ pl,
                                    const void* __restrict__ y,
                                    const void* __restrict__ mask,
                                    float* __restrict__ l0,
                                    const int* __restrict__ flags) {
    if (blockIdx.x < FILL_BLOCKS) {
        int e = blockIdx.x * blockDim.x + threadIdx.x;
        if (e < NE) {
            int is64 = flags[0];
            int r = load_idx(ei, e, is64);
            int c = load_idx(ei, (long long)NE + e, is64);
            if ((unsigned)r < NN && (unsigned)c < NN) {
                int pos = atomicAdd(&cursor[c], 1);
                if ((unsigned)pos < NE) {
                    float w = ew[e];
                    ps[pos] = make_int2(r, __float_as_int(dinv[r] * w * dinv[c]));
                    pl[pos] = make_int2(r, __float_as_int(w));
                }
            }
        }
    } else {
        int idx = (blockIdx.x - FILL_BLOCKS) * blockDim.x + threadIdx.x;
        if (idx < NN * NC) {
            int n = idx / NC, c = idx % NC;
            int yv = load_idx(y, n, flags[2]);
            int mv = flags[1] ? ((const int*)mask)[n]
                              : (int)((const unsigned char*)mask)[n];
            l0[idx] = (mv != 0 && yv == c) ? 1.0f : 0.0f;
        }
    }
}

// ---------------- 40-wide propagate (R7 body, unroll 12) ----------------
// Warp per node. Lanes 0-29 in 3 groups of 10; each group gathers one 160B
// row per edge; 4 edge-triples (12 edges) in flight per iteration with
// independent accumulators. Direct metadata loads (no shfl — they are off
// the dependent path; the scoreboard overlaps them across iterations).
template <bool SELF, bool BIAS>
__device__ __forceinline__ void prop40(int n, int lane,
                                       const float* __restrict__ in,
                                       float* __restrict__ out,
                                       const float* __restrict__ dinv,
                                       const float* __restrict__ bias,
                                       const int* __restrict__ offsets,
                                       const int2* __restrict__ pr) {
    int grp = lane / 10;           // 0..2 active; lanes 30,31 idle
    int sub = lane - grp * 10;     // 0..9
    bool active = (lane < 30);
    int beg = offsets[n], end = offsets[n + 1];

    float4 a0 = make_float4(0.f,0.f,0.f,0.f);
    float4 a1 = a0, a2 = a0, a3 = a0;

    int e = beg;
    for (; e + 12 <= end; e += 12) {
        int2 p0 = make_int2(0,0), p1 = p0, p2 = p0, p3 = p0;
        if (active) {
            p0 = pr[e + grp];
            p1 = pr[e + 3 + grp];
            p2 = pr[e + 6 + grp];
            p3 = pr[e + 9 + grp];
        }
        float w0 = __int_as_float(p0.y), w1 = __int_as_float(p1.y);
        float w2 = __int_as_float(p2.y), w3 = __int_as_float(p3.y);
        if (active) {
            float4 v0 = ((const float4*)(in + (size_t)p0.x * NC))[sub];
            float4 v1 = ((const float4*)(in + (size_t)p1.x * NC))[sub];
            float4 v2 = ((const float4*)(in + (size_t)p2.x * NC))[sub];
            float4 v3 = ((const float4*)(in + (size_t)p3.x * NC))[sub];
            a0.x += w0*v0.x; a0.y += w0*v0.y; a0.z += w0*v0.z; a0.w += w0*v0.w;
            a1.x += w1*v1.x; a1.y += w1*v1.y; a1.z += w1*v1.z; a1.w += w1*v1.w;
            a2.x += w2*v2.x; a2.y += w2*v2.y; a2.z += w2*v2.z; a2.w += w2*v2.w;
            a3.x += w3*v3.x; a3.y += w3*v3.y; a3.z += w3*v3.z; a3.w += w3*v3.w;
        }
    }
    for (; e < end; e += 3) {
        int idx = e + grp;
        if (active && idx < end) {
            int2 p = pr[idx];
            float w = __int_as_float(p.y);
            float4 v = ((const float4*)(in + (size_t)p.x * NC))[sub];
            a0.x += w*v.x; a0.y += w*v.y; a0.z += w*v.z; a0.w += w*v.w;
        }
    }

    float4 acc;
    acc.x = (a0.x + a1.x) + (a2.x + a3.x);
    acc.y = (a0.y + a1.y) + (a2.y + a3.y);
    acc.z = (a0.z + a1.z) + (a2.z + a3.z);
    acc.w = (a0.w + a1.w) + (a2.w + a3.w);

    // combine group partials: lanes 0-9 += lanes 10-19, 20-29
    const unsigned m = 0xFFFFFFFFu;
    float t1, t2;
    t1 = __shfl_sync(m, acc.x, lane + 10); t2 = __shfl_sync(m, acc.x, lane + 20);
    acc.x += t1 + t2;
    t1 = __shfl_sync(m, acc.y, lane + 10); t2 = __shfl_sync(m, acc.y, lane + 20);
    acc.y += t1 + t2;
    t1 = __shfl_sync(m, acc.z, lane + 10); t2 = __shfl_sync(m, acc.z, lane + 20);
    acc.z += t1 + t2;
    t1 = __shfl_sync(m, acc.w, lane + 10); t2 = __shfl_sync(m, acc.w, lane + 20);
    acc.w += t1 + t2;

    if (lane < 10) {
        if (SELF) {
            float dii = dinv[n]; dii *= dii;
            float4 v = ((const float4*)(in + (size_t)n * NC))[lane];
            acc.x += dii * v.x; acc.y += dii * v.y;
            acc.z += dii * v.z; acc.w += dii * v.w;
        }
        if (BIAS) {
            float4 bb = ((const float4*)bias)[lane];
            acc.x += bb.x; acc.y += bb.y; acc.z += bb.z; acc.w += bb.w;
        }
        ((float4*)(out + (size_t)n * NC))[lane] = acc;
    }
}

#define PROP_BLOCKS ((NN + 7) / 8)    // 6250 blocks, warp per node

template <bool LAST>
__global__ __launch_bounds__(256) void prop_pair_kernel(
        const float* __restrict__ sgc_in, float* __restrict__ sgc_out,
        const float* __restrict__ lpa_in, float* __restrict__ lpa_out,
        const float* __restrict__ dinv, const float* __restrict__ bias,
        const int* __restrict__ offsets,
        const int2* __restrict__ ps, const int2* __restrict__ pl) {
    int lane = threadIdx.x & 31;
    int wib  = threadIdx.x >> 5;
    if (blockIdx.x < PROP_BLOCKS) {
        int n = blockIdx.x * 8 + wib;
        if (n < NN) prop40<true, LAST>(n, lane, sgc_in, sgc_out, dinv, bias, offsets, ps);
    } else {
        int n = (blockIdx.x - PROP_BLOCKS) * 8 + wib;
        if (n < NN) prop40<false, false>(n, lane, lpa_in, lpa_out, dinv, bias, offsets, pl);
    }
}

__global__ __launch_bounds__(256) void lpa_final_kernel(
        const float* __restrict__ in, float* __restrict__ out,
        const int* __restrict__ offsets, const int2* __restrict__ pl) {
    int lane = threadIdx.x & 31;
    int n = blockIdx.x * 8 + (threadIdx.x >> 5);
    if (n < NN) prop40<false, false>(n, lane, in, out, nullptr, nullptr, offsets, pl);
}

// ---------------- launch ----------------

extern "C" void kernel_launch(void* const* d_in, const int* in_sizes, int n_in,
                              void* d_out, int out_size) {
    const float* x    = (const float*)d_in[0];
    const void*  ei   = d_in[1];
    const void*  y    = d_in[2];
    const void*  mask = d_in[3];
    const float* ew   = (const float*)d_in[4];
    const float* W    = (const float*)d_in[5];
    const float* b    = (const float*)d_in[6];
    float* out = (float*)d_out;
    float* x_out   = out;
    float* lpa_out = out + NN * NC;

    static float* s = nullptr;
    if (s == nullptr) {
        void* p = nullptr;
        cudaGetSymbolAddress(&p, g_scratch);
        s = (float*)p;
    }
    float* deg     = s + OFF_DEG;
    float* dinv    = s + OFF_DINV;
    int*   counts  = (int*)(s + OFF_COUNTS);
    int*   cursor  = (int*)(s + OFF_CURSOR);
    int*   offsets = (int*)(s + OFF_OFFSETS);
    int*   flags   = (int*)(s + OFF_FLAGS);
    int*   bsum    = (int*)(s + OFF_BSUM);
    int2*  ps      = (int2*)(s + OFF_PAIR_SGC);
    int2*  pl      = (int2*)(s + OFF_PAIR_LPA);
    float* z0      = s + OFF_Z0;
    float* z1      = s + OFF_Z1;
    float* l0      = s + OFF_L0;
    float* l1      = s + OFF_L1;

    const int TB = 256;
    int gE = (NE + TB - 1) / TB;

    // K1: init + sniff + z = x@W
    init_sniff_gemm_kernel<<<INIT_BLOCKS + GEMM_BLOCKS, TB>>>(
        deg, counts, flags, ei, y, mask, x, W, z0);
    // K2-K5: CSR build
    deg_count_kernel<<<gE, TB>>>(ei, ew, deg, counts, flags);
    scanA_kernel<<<SCAN_BLOCKS, SCAN_TB>>>(counts, deg, dinv, bsum);
    scanBC_kernel<<<SCAN_BLOCKS, SCAN_TB>>>(counts, bsum, offsets, cursor);
    fill_lpainit_kernel<<<FILL_BLOCKS + LINIT_BLOCKS, TB>>>(
        ei, ew, dinv, cursor, ps, pl, y, mask, l0, flags);

    // K6: SGC hop1 + LPA iter1   (this is the -s 5 capture target)
    prop_pair_kernel<false><<<2 * PROP_BLOCKS, TB>>>(
        z0, z1, l0, l1, dinv, b, offsets, ps, pl);
    // K7: SGC hop2 (+bias -> x_out) + LPA iter2
    prop_pair_kernel<true><<<2 * PROP_BLOCKS, TB>>>(
        z1, x_out, l1, l0, dinv, b, offsets, ps, pl);
    // K8: LPA iter3 -> lpa_out
    lpa_final_kernel<<<PROP_BLOCKS, TB>>>(l0, lpa_out, offsets, pl);

    (void)in_sizes; (void)n_in; (void)out_size;
}

// round 10
// speedup vs baseline: 1.1197x; 1.1190x over previous
#include <cuda_runtime.h>
#include <cuda_bf16.h>
#include <cstdint>

#define NN 50000
#define NE 800000
#define NF 96
#define NC 40

#define SCAN_TB 256
#define SCAN_BLOCKS ((NN + SCAN_TB - 1) / SCAN_TB)   // 196

// ---------------- flat static device scratch ----------------
#define OFF_DEG      0
#define OFF_DINV     (OFF_DEG + NN)
#define OFF_COUNTS   (OFF_DINV + NN)
#define OFF_CURSOR   (OFF_COUNTS + NN)
#define OFF_OFFSETS  (OFF_CURSOR + NN)              // NN+1 ints
#define OFF_FLAGS    (OFF_OFFSETS + NN + 8)         // 4 ints
#define OFF_BSUM     (OFF_FLAGS + 8)                // 256 ints
#define OFF_PAIR_SGC (OFF_BSUM + 256)               // NE int2 (src, norm)
#define OFF_PAIR_LPA (OFF_PAIR_SGC + 2 * NE)        // NE int2 (src, ew)
#define OFF_Z0       (OFF_PAIR_LPA + 2 * NE)        // NN*NC
#define OFF_Z1       (OFF_Z0 + NN * NC)
#define OFF_L0       (OFF_Z1 + NN * NC)
#define OFF_L1       (OFF_L0 + NN * NC)
#define SCRATCH_ELEMS (OFF_L1 + NN * NC + 64)

__device__ __align__(256) float g_scratch[SCRATCH_ELEMS];

// flags[0]: edge_index is int64; flags[1]: mask is 4-byte; flags[2]: y is int64
__device__ __forceinline__ int load_idx(const void* p, long long i, int is64) {
    return is64 ? (int)((const long long*)p)[i] : ((const int*)p)[i];
}

// ---------------- K1: init + sniff + gemm (z = x @ W, NO bias) ----------------
#define GEMM_ROWS 32
#define GEMM_BLOCKS ((NN + GEMM_ROWS - 1) / GEMM_ROWS)   // 1563
#define INIT_BLOCKS ((NN + 255) / 256)                    // 196

__global__ void init_sniff_gemm_kernel(float* __restrict__ deg,
                                       int* __restrict__ counts,
                                       int* __restrict__ flags,
                                       const void* __restrict__ ei,
                                       const void* __restrict__ y,
                                       const void* __restrict__ mask,
                                       const float* __restrict__ x,
                                       const float* __restrict__ W,
                                       float* __restrict__ z) {
    if (blockIdx.x < INIT_BLOCKS) {
        int i = blockIdx.x * blockDim.x + threadIdx.x;
        if (i < NN) { deg[i] = 1.0f; counts[i] = 0; }
        if (blockIdx.x == 0) {
            __shared__ int narrow[3];
            int tid = threadIdx.x;
            if (tid < 3) narrow[tid] = 0;
            __syncthreads();
            const int* ei32 = (const int*)ei;
            const int* y32  = (const int*)y;
            const unsigned char* m8 = (const unsigned char*)mask;
            if (ei32[2 * tid + 1] != 0) narrow[0] = 1;
            if (y32[2 * tid + 1]  != 0) narrow[2] = 1;
            for (int t = tid; t < 4096; t += 256)
                if ((t & 3) != 0 && m8[t] != 0) narrow[1] = 1;
            __syncthreads();
            if (tid < 3) flags[tid] = narrow[tid] ? 0 : 1;
        }
    } else {
        __shared__ float sW[NF * NC];
        __shared__ float sH[GEMM_ROWS * NF];
        int tid = threadIdx.x;
        int row0 = (blockIdx.x - INIT_BLOCKS) * GEMM_ROWS;
        for (int i = tid; i < NF * NC; i += 256) sW[i] = W[i];
        int nrows = min(GEMM_ROWS, NN - row0);
        int nelem = nrows * NF;
        const float* hp = x + (size_t)row0 * NF;
        for (int i = tid; i < nelem; i += 256) sH[i] = hp[i];
        __syncthreads();
        int nout = nrows * NC;
        for (int o = tid; o < nout; o += 256) {
            int r = o / NC, c = o % NC;
            float acc = 0.0f;
            const float* hr = &sH[r * NF];
            #pragma unroll 8
            for (int k = 0; k < NF; k++) acc += hr[k] * sW[k * NC + c];
            z[(size_t)(row0 + r) * NC + c] = acc;
        }
    }
}

__global__ void deg_count_kernel(const void* __restrict__ ei,
                                 const float* __restrict__ ew,
                                 float* __restrict__ deg,
                                 int* __restrict__ counts,
                                 const int* __restrict__ flags) {
    int e = blockIdx.x * blockDim.x + threadIdx.x;
    if (e < NE) {
        int c = load_idx(ei, (long long)NE + e, flags[0]);
        if ((unsigned)c < NN) {
            atomicAdd(&deg[c], ew[e]);
            atomicAdd(&counts[c], 1);
        }
    }
}

// ---- Phase A: per-block reduce of counts + fused dinv ----
__global__ void scanA_kernel(const int* __restrict__ counts,
                             const float* __restrict__ deg,
                             float* __restrict__ dinv,
                             int* __restrict__ bsum) {
    __shared__ int sh[SCAN_TB];
    int i = blockIdx.x * SCAN_TB + threadIdx.x;
    int v = (i < NN) ? counts[i] : 0;
    if (i < NN) dinv[i] = rsqrtf(deg[i]);
    sh[threadIdx.x] = v;
    __syncthreads();
    for (int off = SCAN_TB / 2; off > 0; off >>= 1) {
        if (threadIdx.x < off) sh[threadIdx.x] += sh[threadIdx.x + off];
        __syncthreads();
    }
    if (threadIdx.x == 0) bsum[blockIdx.x] = sh[0];
}

// ---- Phase BC merged: every block redundantly scans block sums, then local scan ----
__global__ void scanBC_kernel(const int* __restrict__ counts,
                              const int* __restrict__ bsum,
                              int* __restrict__ offsets,
                              int* __restrict__ cursor) {
    __shared__ int sb[SCAN_TB];
    __shared__ int sh[SCAN_TB];
    int t = threadIdx.x;
    int bv = (t < SCAN_BLOCKS) ? bsum[t] : 0;
    sb[t] = bv;
    __syncthreads();
    for (int off = 1; off < SCAN_TB; off <<= 1) {
        int u = (t >= off) ? sb[t - off] : 0;
        __syncthreads();
        sb[t] += u;
        __syncthreads();
    }
    int blockPrefix = (blockIdx.x == 0) ? 0 : sb[blockIdx.x - 1];
    if (blockIdx.x == 0 && t == 0) offsets[NN] = sb[SCAN_BLOCKS - 1];

    int i = blockIdx.x * SCAN_TB + t;
    int v = (i < NN) ? counts[i] : 0;
    sh[t] = v;
    __syncthreads();
    for (int off = 1; off < SCAN_TB; off <<= 1) {
        int u = (t >= off) ? sh[t - off] : 0;
        __syncthreads();
        sh[t] += u;
        __syncthreads();
    }
    if (i < NN) {
        int excl = blockPrefix + sh[t] - v;
        offsets[i] = excl;
        cursor[i]  = excl;
    }
}

// ---- fill CSR (+ fused LPA one-hot init) ----
#define FILL_BLOCKS  ((NE + 255) / 256)
#define LINIT_BLOCKS ((NN * NC + 255) / 256)

__global__ void fill_lpainit_kernel(const void* __restrict__ ei,
                                    const float* __restrict__ ew,
                                    const float* __restrict__ dinv,
                                    int* __restrict__ cursor,
                                    int2* __restrict__ ps,
                                    int2* __restrict__ pl,
                                    const void* __restrict__ y,
                                    const void* __restrict__ mask,
                                    float* __restrict__ l0,
                                    const int* __restrict__ flags) {
    if (blockIdx.x < FILL_BLOCKS) {
        int e = blockIdx.x * blockDim.x + threadIdx.x;
        if (e < NE) {
            int is64 = flags[0];
            int r = load_idx(ei, e, is64);
            int c = load_idx(ei, (long long)NE + e, is64);
            if ((unsigned)r < NN && (unsigned)c < NN) {
                int pos = atomicAdd(&cursor[c], 1);
                if ((unsigned)pos < NE) {
                    float w = ew[e];
                    ps[pos] = make_int2(r, __float_as_int(dinv[r] * w * dinv[c]));
                    pl[pos] = make_int2(r, __float_as_int(w));
                }
            }
        }
    } else {
        int idx = (blockIdx.x - FILL_BLOCKS) * blockDim.x + threadIdx.x;
        if (idx < NN * NC) {
            int n = idx / NC, c = idx % NC;
            int yv = load_idx(y, n, flags[2]);
            int mv = flags[1] ? ((const int*)mask)[n]
                              : (int)((const unsigned char*)mask)[n];
            l0[idx] = (mv != 0 && yv == c) ? 1.0f : 0.0f;
        }
    }
}

// ---------------- 40-wide propagate (exact R7 body: 6-edge unroll) ----------
template <bool SELF, bool BIAS>
__device__ __forceinline__ void prop40(int n, int lane,
                                       const float* __restrict__ in,
                                       float* __restrict__ out,
                                       const float* __restrict__ dinv,
                                       const float* __restrict__ bias,
                                       const int* __restrict__ offsets,
                                       const int2* __restrict__ pr) {
    int grp = lane / 10;           // 0..2 active; lanes 30,31 idle
    int sub = lane - grp * 10;     // 0..9
    bool active = (lane < 30);
    float4 acc = make_float4(0.f, 0.f, 0.f, 0.f);
    int beg = offsets[n], end = offsets[n + 1];
    int e = beg;
    for (; e + 6 <= end; e += 6) {
        int2 pa, pb;
        float wa = 0.f, wb = 0.f; int sa = 0, sb = 0;
        if (active) {
            pa = pr[e + grp];     sa = pa.x; wa = __int_as_float(pa.y);
            pb = pr[e + 3 + grp]; sb = pb.x; wb = __int_as_float(pb.y);
        }
        float4 va = make_float4(0.f,0.f,0.f,0.f), vb = va;
        if (wa != 0.f) va = ((const float4*)(in + (size_t)sa * NC))[sub];
        if (wb != 0.f) vb = ((const float4*)(in + (size_t)sb * NC))[sub];
        acc.x += wa * va.x + wb * vb.x;
        acc.y += wa * va.y + wb * vb.y;
        acc.z += wa * va.z + wb * vb.z;
        acc.w += wa * va.w + wb * vb.w;
    }
    for (; e < end; e += 3) {
        int idx = e + grp;
        float w = 0.f; int s = 0;
        if (active && idx < end) {
            int2 p = pr[idx]; s = p.x; w = __int_as_float(p.y);
        }
        if (w != 0.f) {
            float4 v = ((const float4*)(in + (size_t)s * NC))[sub];
            acc.x += w * v.x; acc.y += w * v.y; acc.z += w * v.z; acc.w += w * v.w;
        }
    }
    // combine partials from lane+10, lane+20 (valid on lanes 0-9)
    unsigned m = 0xFFFFFFFFu;
    float t1, t2;
    t1 = __shfl_sync(m, acc.x, lane + 10); t2 = __shfl_sync(m, acc.x, lane + 20);
    acc.x += t1 + t2;
    t1 = __shfl_sync(m, acc.y, lane + 10); t2 = __shfl_sync(m, acc.y, lane + 20);
    acc.y += t1 + t2;
    t1 = __shfl_sync(m, acc.z, lane + 10); t2 = __shfl_sync(m, acc.z, lane + 20);
    acc.z += t1 + t2;
    t1 = __shfl_sync(m, acc.w, lane + 10); t2 = __shfl_sync(m, acc.w, lane + 20);
    acc.w += t1 + t2;

    if (lane < 10) {
        if (SELF) {
            float dii = dinv[n]; dii *= dii;
            float4 v = ((const float4*)(in + (size_t)n * NC))[lane];
            acc.x += dii * v.x; acc.y += dii * v.y;
            acc.z += dii * v.z; acc.w += dii * v.w;
        }
        if (BIAS) {
            float4 bb = ((const float4*)bias)[lane];
            acc.x += bb.x; acc.y += bb.y; acc.z += bb.z; acc.w += bb.w;
        }
        ((float4*)(out + (size_t)n * NC))[lane] = acc;
    }
}

#define PROP_BLOCKS ((NN + 7) / 8)    // 6250 blocks per role, warp per node

// Parity-interleaved roles: even blocks = SGC, odd blocks = LPA.
// Both roles co-resident from the first wave -> mixed latency chains.
template <bool LAST>
__global__ __launch_bounds__(256) void prop_pair_kernel(
        const float* __restrict__ sgc_in, float* __restrict__ sgc_out,
        const float* __restrict__ lpa_in, float* __restrict__ lpa_out,
        const float* __restrict__ dinv, const float* __restrict__ bias,
        const int* __restrict__ offsets,
        const int2* __restrict__ ps, const int2* __restrict__ pl) {
    int lane = threadIdx.x & 31;
    int wib  = threadIdx.x >> 5;
    int role = blockIdx.x & 1;
    int n = (blockIdx.x >> 1) * 8 + wib;
    if (n >= NN) return;
    if (role == 0) {
        prop40<true, LAST>(n, lane, sgc_in, sgc_out, dinv, bias, offsets, ps);
    } else {
        prop40<false, false>(n, lane, lpa_in, lpa_out, dinv, bias, offsets, pl);
    }
}

__global__ __launch_bounds__(256) void lpa_final_kernel(
        const float* __restrict__ in, float* __restrict__ out,
        const int* __restrict__ offsets, const int2* __restrict__ pl) {
    int lane = threadIdx.x & 31;
    int n = blockIdx.x * 8 + (threadIdx.x >> 5);
    if (n < NN) prop40<false, false>(n, lane, in, out, nullptr, nullptr, offsets, pl);
}

// ---------------- launch ----------------

extern "C" void kernel_launch(void* const* d_in, const int* in_sizes, int n_in,
                              void* d_out, int out_size) {
    const float* x    = (const float*)d_in[0];
    const void*  ei   = d_in[1];
    const void*  y    = d_in[2];
    const void*  mask = d_in[3];
    const float* ew   = (const float*)d_in[4];
    const float* W    = (const float*)d_in[5];
    const float* b    = (const float*)d_in[6];
    float* out = (float*)d_out;
    float* x_out   = out;
    float* lpa_out = out + NN * NC;

    static float* s = nullptr;
    if (s == nullptr) {
        void* p = nullptr;
        cudaGetSymbolAddress(&p, g_scratch);
        s = (float*)p;
    }
    float* deg     = s + OFF_DEG;
    float* dinv    = s + OFF_DINV;
    int*   counts  = (int*)(s + OFF_COUNTS);
    int*   cursor  = (int*)(s + OFF_CURSOR);
    int*   offsets = (int*)(s + OFF_OFFSETS);
    int*   flags   = (int*)(s + OFF_FLAGS);
    int*   bsum    = (int*)(s + OFF_BSUM);
    int2*  ps      = (int2*)(s + OFF_PAIR_SGC);
    int2*  pl      = (int2*)(s + OFF_PAIR_LPA);
    float* z0      = s + OFF_Z0;
    float* z1      = s + OFF_Z1;
    float* l0      = s + OFF_L0;
    float* l1      = s + OFF_L1;

    const int TB = 256;
    int gE = (NE + TB - 1) / TB;

    // K1: init + sniff + z = x@W
    init_sniff_gemm_kernel<<<INIT_BLOCKS + GEMM_BLOCKS, TB>>>(
        deg, counts, flags, ei, y, mask, x, W, z0);
    // K2-K5: CSR build
    deg_count_kernel<<<gE, TB>>>(ei, ew, deg, counts, flags);
    scanA_kernel<<<SCAN_BLOCKS, SCAN_TB>>>(counts, deg, dinv, bsum);
    scanBC_kernel<<<SCAN_BLOCKS, SCAN_TB>>>(counts, bsum, offsets, cursor);
    fill_lpainit_kernel<<<FILL_BLOCKS + LINIT_BLOCKS, TB>>>(
        ei, ew, dinv, cursor, ps, pl, y, mask, l0, flags);

    // K6: SGC hop1 + LPA iter1 (parity-interleaved roles)
    prop_pair_kernel<false><<<2 * PROP_BLOCKS, TB>>>(
        z0, z1, l0, l1, dinv, b, offsets, ps, pl);
    // K7: SGC hop2 (+bias -> x_out) + LPA iter2
    prop_pair_kernel<true><<<2 * PROP_BLOCKS, TB>>>(
        z1, x_out, l1, l0, dinv, b, offsets, ps, pl);
    // K8: LPA iter3 -> lpa_out
    lpa_final_kernel<<<PROP_BLOCKS, TB>>>(l0, lpa_out, offsets, pl);

    (void)in_sizes; (void)n_in; (void)out_size;
}

// round 11
// speedup vs baseline: 1.1728x; 1.0475x over previous
#include <cuda_runtime.h>
#include <cuda_bf16.h>
#include <cstdint>

#define NN 50000
#define NE 800000
#define NF 96
#define NC 40

#define SCAN_TB 256
#define SCAN_BLOCKS ((NN + SCAN_TB - 1) / SCAN_TB)   // 196

#define BUILD_GRID 592     // 4 blocks per SM on 148 SMs -> all resident (no deadlock)
#define BUILD_TB   256

// ---------------- flat static device scratch ----------------
#define OFF_DEG      0
#define OFF_DINV     (OFF_DEG + NN)
#define OFF_COUNTS   (OFF_DINV + NN)
#define OFF_CURSOR   (OFF_COUNTS + NN)
#define OFF_OFFSETS  (OFF_CURSOR + NN)              // NN+1 ints
#define OFF_FLAGS    (OFF_OFFSETS + NN + 8)         // 4 ints
#define OFF_BSUM     (OFF_FLAGS + 8)                // 256 ints
#define OFF_PAIR_SGC (OFF_BSUM + 256)               // NE int2 (src, norm)
#define OFF_PAIR_LPA (OFF_PAIR_SGC + 2 * NE)        // NE int2 (src, ew)
#define OFF_Z0       (OFF_PAIR_LPA + 2 * NE)        // NN*NC
#define OFF_Z1       (OFF_Z0 + NN * NC)
#define OFF_L0       (OFF_Z1 + NN * NC)
#define OFF_L1       (OFF_L0 + NN * NC)
#define SCRATCH_ELEMS (OFF_L1 + NN * NC + 64)

__device__ __align__(256) float g_scratch[SCRATCH_ELEMS];

// Grid-barrier counters: zero-initialized at module load, NEVER reset.
// Monotonic epochs make them correct across graph replays.
__device__ int g_barriers[8];

__device__ __forceinline__ void grid_barrier(int id) {
    __syncthreads();
    if (threadIdx.x == 0) {
        __threadfence();                       // release: drain block's stores to L2
        int old = atomicAdd(&g_barriers[id], 1);
        int target = (old / (int)gridDim.x + 1) * (int)gridDim.x;
        while (atomicAdd(&g_barriers[id], 0) < target) { __nanosleep(200); }
        __threadfence();                       // acquire: CCTL.IVALL -> fresh L1 reads
    }
    __syncthreads();
}

// flags[0]: edge_index is int64; flags[1]: mask is 4-byte; flags[2]: y is int64
__device__ __forceinline__ int load_idx(const void* p, long long i, int is64) {
    return is64 ? (int)((const long long*)p)[i] : ((const int*)p)[i];
}

#define GEMM_ROWS 32
#define GEMM_TILES ((NN + GEMM_ROWS - 1) / GEMM_ROWS)   // 1563

// ================== ONE fused build kernel ==================
// P0: init deg/counts + sniff (block 0) + gemm z = x@W (grid-stride tiles)
// P1: deg_count (atomics)
// P2: per-chunk reduce of counts -> bsum; dinv
// P3: redundant bsum scan + local scan -> offsets, cursor
// P4: fill CSR pairs + LPA one-hot init
__global__ __launch_bounds__(BUILD_TB, 4)
void build_kernel(float* __restrict__ deg, int* __restrict__ counts,
                  int* __restrict__ flags, int* __restrict__ bsum,
                  int* __restrict__ offsets, int* __restrict__ cursor,
                  float* __restrict__ dinv,
                  int2* __restrict__ ps, int2* __restrict__ pl,
                  float* __restrict__ z, float* __restrict__ l0,
                  const void* __restrict__ ei, const void* __restrict__ y,
                  const void* __restrict__ mask,
                  const float* __restrict__ ew,
                  const float* __restrict__ x, const float* __restrict__ W) {
    __shared__ __align__(16) char sh_pool[(NF * NC + GEMM_ROWS * NF) * 4]; // 27648 B
    const int tid = threadIdx.x;
    const int gsz = gridDim.x * blockDim.x;
    const int gtid = blockIdx.x * blockDim.x + tid;

    // ---------------- P0 ----------------
    for (int i = gtid; i < NN; i += gsz) { deg[i] = 1.0f; counts[i] = 0; }

    if (blockIdx.x == 0) {
        __shared__ int narrow[3];
        if (tid < 3) narrow[tid] = 0;
        __syncthreads();
        const int* ei32 = (const int*)ei;
        const int* y32  = (const int*)y;
        const unsigned char* m8 = (const unsigned char*)mask;
        if (ei32[2 * tid + 1] != 0) narrow[0] = 1;
        if (y32[2 * tid + 1]  != 0) narrow[2] = 1;
        for (int t = tid; t < 4096; t += 256)
            if ((t & 3) != 0 && m8[t] != 0) narrow[1] = 1;
        __syncthreads();
        if (tid < 3) flags[tid] = narrow[tid] ? 0 : 1;
    }

    // gemm: z = x @ W  (each block loads W once, loops over row tiles)
    {
        float* sW = (float*)sh_pool;
        float* sH = sW + NF * NC;
        for (int i = tid; i < NF * NC; i += BUILD_TB) sW[i] = W[i];
        for (int tile = blockIdx.x; tile < GEMM_TILES; tile += gridDim.x) {
            int row0 = tile * GEMM_ROWS;
            int nrows = min(GEMM_ROWS, NN - row0);
            int nelem = nrows * NF;
            const float* hp = x + (size_t)row0 * NF;
            __syncthreads();
            for (int i = tid; i < nelem; i += BUILD_TB) sH[i] = hp[i];
            __syncthreads();
            int nout = nrows * NC;
            for (int o = tid; o < nout; o += BUILD_TB) {
                int r = o / NC, c = o % NC;
                float acc = 0.0f;
                const float* hr = &sH[r * NF];
                #pragma unroll 8
                for (int k = 0; k < NF; k++) acc += hr[k] * sW[k * NC + c];
                z[(size_t)(row0 + r) * NC + c] = acc;
            }
        }
    }
    grid_barrier(0);

    // ---------------- P1: degree/count atomics ----------------
    {
        int is64 = flags[0];
        for (int e = gtid; e < NE; e += gsz) {
            int c = load_idx(ei, (long long)NE + e, is64);
            if ((unsigned)c < NN) {
                atomicAdd(&deg[c], ew[e]);
                atomicAdd(&counts[c], 1);
            }
        }
    }
    grid_barrier(1);

    // ---------------- P2: chunk reduce + dinv ----------------
    {
        int* sh = (int*)sh_pool;
        if (blockIdx.x < SCAN_BLOCKS) {
            int i = blockIdx.x * SCAN_TB + tid;
            sh[tid] = (i < NN) ? counts[i] : 0;
            __syncthreads();
            for (int off = SCAN_TB / 2; off > 0; off >>= 1) {
                if (tid < off) sh[tid] += sh[tid + off];
                __syncthreads();
            }
            if (tid == 0) bsum[blockIdx.x] = sh[0];
        }
        for (int i = gtid; i < NN; i += gsz) dinv[i] = rsqrtf(deg[i]);
    }
    grid_barrier(2);

    // ---------------- P3: scan -> offsets, cursor ----------------
    if (blockIdx.x < SCAN_BLOCKS) {
        int* sb = (int*)sh_pool;
        int* sh = sb + SCAN_TB;
        int bv = (tid < SCAN_BLOCKS) ? bsum[tid] : 0;
        sb[tid] = bv;
        __syncthreads();
        for (int off = 1; off < SCAN_TB; off <<= 1) {
            int u = (tid >= off) ? sb[tid - off] : 0;
            __syncthreads();
            sb[tid] += u;
            __syncthreads();
        }
        int blockPrefix = (blockIdx.x == 0) ? 0 : sb[blockIdx.x - 1];
        if (blockIdx.x == 0 && tid == 0) offsets[NN] = sb[SCAN_BLOCKS - 1];

        int i = blockIdx.x * SCAN_TB + tid;
        int v = (i < NN) ? counts[i] : 0;
        sh[tid] = v;
        __syncthreads();
        for (int off = 1; off < SCAN_TB; off <<= 1) {
            int u = (tid >= off) ? sh[tid - off] : 0;
            __syncthreads();
            sh[tid] += u;
            __syncthreads();
        }
        if (i < NN) {
            int excl = blockPrefix + sh[tid] - v;
            offsets[i] = excl;
            cursor[i]  = excl;
        }
    }
    grid_barrier(3);

    // ---------------- P4: fill CSR + LPA one-hot init ----------------
    {
        int is64 = flags[0];
        for (int e = gtid; e < NE; e += gsz) {
            int r = load_idx(ei, e, is64);
            int c = load_idx(ei, (long long)NE + e, is64);
            if ((unsigned)r < NN && (unsigned)c < NN) {
                int pos = atomicAdd(&cursor[c], 1);
                if ((unsigned)pos < NE) {
                    float w = ew[e];
                    ps[pos] = make_int2(r, __float_as_int(dinv[r] * w * dinv[c]));
                    pl[pos] = make_int2(r, __float_as_int(w));
                }
            }
        }
        int m4  = flags[1];
        int y64 = flags[2];
        for (int idx = gtid; idx < NN * NC; idx += gsz) {
            int n = idx / NC, c = idx % NC;
            int yv = load_idx(y, n, y64);
            int mv = m4 ? ((const int*)mask)[n]
                        : (int)((const unsigned char*)mask)[n];
            l0[idx] = (mv != 0 && yv == c) ? 1.0f : 0.0f;
        }
    }
}

// ---------------- 40-wide propagate (exact R10 body) ----------
template <bool SELF, bool BIAS>
__device__ __forceinline__ void prop40(int n, int lane,
                                       const float* __restrict__ in,
                                       float* __restrict__ out,
                                       const float* __restrict__ dinv,
                                       const float* __restrict__ bias,
                                       const int* __restrict__ offsets,
                                       const int2* __restrict__ pr) {
    int grp = lane / 10;           // 0..2 active; lanes 30,31 idle
    int sub = lane - grp * 10;     // 0..9
    bool active = (lane < 30);
    float4 acc = make_float4(0.f, 0.f, 0.f, 0.f);
    int beg = offsets[n], end = offsets[n + 1];
    int e = beg;
    for (; e + 6 <= end; e += 6) {
        int2 pa, pb;
        float wa = 0.f, wb = 0.f; int sa = 0, sb = 0;
        if (active) {
            pa = pr[e + grp];     sa = pa.x; wa = __int_as_float(pa.y);
            pb = pr[e + 3 + grp]; sb = pb.x; wb = __int_as_float(pb.y);
        }
        float4 va = make_float4(0.f,0.f,0.f,0.f), vb = va;
        if (wa != 0.f) va = ((const float4*)(in + (size_t)sa * NC))[sub];
        if (wb != 0.f) vb = ((const float4*)(in + (size_t)sb * NC))[sub];
        acc.x += wa * va.x + wb * vb.x;
        acc.y += wa * va.y + wb * vb.y;
        acc.z += wa * va.z + wb * vb.z;
        acc.w += wa * va.w + wb * vb.w;
    }
    for (; e < end; e += 3) {
        int idx = e + grp;
        float w = 0.f; int s = 0;
        if (active && idx < end) {
            int2 p = pr[idx]; s = p.x; w = __int_as_float(p.y);
        }
        if (w != 0.f) {
            float4 v = ((const float4*)(in + (size_t)s * NC))[sub];
            acc.x += w * v.x; acc.y += w * v.y; acc.z += w * v.z; acc.w += w * v.w;
        }
    }
    unsigned m = 0xFFFFFFFFu;
    float t1, t2;
    t1 = __shfl_sync(m, acc.x, lane + 10); t2 = __shfl_sync(m, acc.x, lane + 20);
    acc.x += t1 + t2;
    t1 = __shfl_sync(m, acc.y, lane + 10); t2 = __shfl_sync(m, acc.y, lane + 20);
    acc.y += t1 + t2;
    t1 = __shfl_sync(m, acc.z, lane + 10); t2 = __shfl_sync(m, acc.z, lane + 20);
    acc.z += t1 + t2;
    t1 = __shfl_sync(m, acc.w, lane + 10); t2 = __shfl_sync(m, acc.w, lane + 20);
    acc.w += t1 + t2;

    if (lane < 10) {
        if (SELF) {
            float dii = dinv[n]; dii *= dii;
            float4 v = ((const float4*)(in + (size_t)n * NC))[lane];
            acc.x += dii * v.x; acc.y += dii * v.y;
            acc.z += dii * v.z; acc.w += dii * v.w;
        }
        if (BIAS) {
            float4 bb = ((const float4*)bias)[lane];
            acc.x += bb.x; acc.y += bb.y; acc.z += bb.z; acc.w += bb.w;
        }
        ((float4*)(out + (size_t)n * NC))[lane] = acc;
    }
}

#define PROP_BLOCKS ((NN + 7) / 8)    // 6250 blocks per role

template <bool LAST>
__global__ __launch_bounds__(256) void prop_pair_kernel(
        const float* __restrict__ sgc_in, float* __restrict__ sgc_out,
        const float* __restrict__ lpa_in, float* __restrict__ lpa_out,
        const float* __restrict__ dinv, const float* __restrict__ bias,
        const int* __restrict__ offsets,
        const int2* __restrict__ ps, const int2* __restrict__ pl) {
    int lane = threadIdx.x & 31;
    int wib  = threadIdx.x >> 5;
    int role = blockIdx.x & 1;
    int n = (blockIdx.x >> 1) * 8 + wib;
    if (n >= NN) return;
    if (role == 0) {
        prop40<true, LAST>(n, lane, sgc_in, sgc_out, dinv, bias, offsets, ps);
    } else {
        prop40<false, false>(n, lane, lpa_in, lpa_out, dinv, bias, offsets, pl);
    }
}

__global__ __launch_bounds__(256) void lpa_final_kernel(
        const float* __restrict__ in, float* __restrict__ out,
        const int* __restrict__ offsets, const int2* __restrict__ pl) {
    int lane = threadIdx.x & 31;
    int n = blockIdx.x * 8 + (threadIdx.x >> 5);
    if (n < NN) prop40<false, false>(n, lane, in, out, nullptr, nullptr, offsets, pl);
}

// ---------------- launch ----------------

extern "C" void kernel_launch(void* const* d_in, const int* in_sizes, int n_in,
                              void* d_out, int out_size) {
    const float* x    = (const float*)d_in[0];
    const void*  ei   = d_in[1];
    const void*  y    = d_in[2];
    const void*  mask = d_in[3];
    const float* ew   = (const float*)d_in[4];
    const float* W    = (const float*)d_in[5];
    const float* b    = (const float*)d_in[6];
    float* out = (float*)d_out;
    float* x_out   = out;
    float* lpa_out = out + NN * NC;

    static float* s = nullptr;
    if (s == nullptr) {
        void* p = nullptr;
        cudaGetSymbolAddress(&p, g_scratch);
        s = (float*)p;
    }
    float* deg     = s + OFF_DEG;
    float* dinv    = s + OFF_DINV;
    int*   counts  = (int*)(s + OFF_COUNTS);
    int*   cursor  = (int*)(s + OFF_CURSOR);
    int*   offsets = (int*)(s + OFF_OFFSETS);
    int*   flags   = (int*)(s + OFF_FLAGS);
    int*   bsum    = (int*)(s + OFF_BSUM);
    int2*  ps      = (int2*)(s + OFF_PAIR_SGC);
    int2*  pl      = (int2*)(s + OFF_PAIR_LPA);
    float* z0      = s + OFF_Z0;
    float* z1      = s + OFF_Z1;
    float* l0      = s + OFF_L0;
    float* l1      = s + OFF_L1;

    // K0: entire CSR build + sniff + gemm in one kernel (device grid barriers)
    build_kernel<<<BUILD_GRID, BUILD_TB>>>(
        deg, counts, flags, bsum, offsets, cursor, dinv,
        ps, pl, z0, l0, ei, y, mask, ew, x, W);

    // K1: SGC hop1 + LPA iter1 (parity-interleaved roles)
    prop_pair_kernel<false><<<2 * PROP_BLOCKS, 256>>>(
        z0, z1, l0, l1, dinv, b, offsets, ps, pl);
    // K2: SGC hop2 (+bias -> x_out) + LPA iter2
    prop_pair_kernel<true><<<2 * PROP_BLOCKS, 256>>>(
        z1, x_out, l1, l0, dinv, b, offsets, ps, pl);
    // K3: LPA iter3 -> lpa_out   (capture index 3 -> first real prop profile)
    lpa_final_kernel<<<PROP_BLOCKS, 256>>>(l0, lpa_out, offsets, pl);

    (void)in_sizes; (void)n_in; (void)out_size;
}